// round 9
// baseline (speedup 1.0000x reference)
#include <cuda_runtime.h>

// Fixed shapes
#define BB 8
#define HH 512
#define WW 512
#define NPIX (BB * HH * WW)          // 2,097,152
#define HW (HH * WW)                 // 262,144
#define EPSF 1e-10f
#define PPT 8                        // pixels per thread
#define NBLOCKS ((NPIX / PPT) / 256) // 1024

__device__ double g_acc = 0.0;
__device__ unsigned int g_ticket = 0;

__device__ __forceinline__ float clipf(float v) {
    return fminf(fmaxf(v, EPSF), 1.0f - EPSF);
}

__device__ __forceinline__ void ld8(float* dst, const float* __restrict__ p) {
    const float4 a = *reinterpret_cast<const float4*>(p);
    const float4 b = *reinterpret_cast<const float4*>(p + 4);
    dst[0]=a.x; dst[1]=a.y; dst[2]=a.z; dst[3]=a.w;
    dst[4]=b.x; dst[5]=b.y; dst[6]=b.z; dst[7]=b.w;
}

// One thread = 8 consecutive pixels (two aligned float4s). Warp spans 1KB
// contiguous per stream -> longer DRAM bursts, half the index/branch overhead.
__global__ void __launch_bounds__(256) flow_loss_kernel(
    const float* __restrict__ roi,
    const float* __restrict__ hm0,  const float* __restrict__ hm1,  const float* __restrict__ hm2,
    const float* __restrict__ r1pf, const float* __restrict__ r1pb,
    const float* __restrict__ r1nf, const float* __restrict__ r1nb,
    const float* __restrict__ r0f,  const float* __restrict__ r0b,
    const float* __restrict__ r2f,  const float* __restrict__ r2b,
    const float* __restrict__ f01f, const float* __restrict__ f10b,
    const float* __restrict__ f12f, const float* __restrict__ f21b,
    float* __restrict__ out)
{
    const int t    = blockIdx.x * blockDim.x + threadIdx.x;   // 0 .. NPIX/8-1
    const int idx  = t * PPT;

    const int x0 = idx & (WW - 1);           // multiple of 8
    const int y  = (idx >> 9) & (HH - 1);
    const int n  = idx >> 18;

    // ---- rec losses ----
    float mm[PPT], h0a[PPT], h1a[PPT], h2a[PPT];
    ld8(mm,  roi + idx);
    ld8(h0a, hm0 + idx);
    ld8(h1a, hm1 + idx);
    ld8(h2a, hm2 + idx);

    float wpre[PPT], wpost[PPT], pix[PPT];
    #pragma unroll
    for (int j = 0; j < PPT; j++) {
        wpre[j]  = 1.0f + fabsf(h0a[j] - h1a[j]);
        wpost[j] = 1.0f + fabsf(h1a[j] - h2a[j]);
        pix[j] = 0.0f;
    }

    {
        float v[PPT];
        ld8(v, r1pf + idx);
        #pragma unroll
        for (int j = 0; j < PPT; j++) { const float d = v[j] - h1a[j]; pix[j] += d*d*wpre[j]*0.25f; }
        ld8(v, r1pb + idx);
        #pragma unroll
        for (int j = 0; j < PPT; j++) { const float d = v[j] - h1a[j]; pix[j] += d*d*wpre[j]*0.25f; }
        ld8(v, r1nf + idx);
        #pragma unroll
        for (int j = 0; j < PPT; j++) { const float d = v[j] - h1a[j]; pix[j] += d*d*wpost[j]*0.25f; }
        ld8(v, r1nb + idx);
        #pragma unroll
        for (int j = 0; j < PPT; j++) { const float d = v[j] - h1a[j]; pix[j] += d*d*wpost[j]*0.25f; }
        ld8(v, r0f + idx);
        #pragma unroll
        for (int j = 0; j < PPT; j++) { const float d = v[j] - h0a[j]; pix[j] += d*d*wpre[j]*0.5f; }
        ld8(v, r0b + idx);
        #pragma unroll
        for (int j = 0; j < PPT; j++) { const float d = v[j] - h0a[j]; pix[j] += d*d*wpre[j]*0.5f; }
        ld8(v, r2f + idx);
        #pragma unroll
        for (int j = 0; j < PPT; j++) { const float d = v[j] - h2a[j]; pix[j] += d*d*wpost[j]*0.5f; }
        ld8(v, r2b + idx);
        #pragma unroll
        for (int j = 0; j < PPT; j++) { const float d = v[j] - h2a[j]; pix[j] += d*d*wpost[j]*0.5f; }
    }

    float acc = 0.0f;
    #pragma unroll
    for (int j = 0; j < PPT; j++) acc += mm[j] * pix[j];

    // ---- flow consistency ----
    float csum[PPT];
    #pragma unroll
    for (int j = 0; j < PPT; j++) csum[j] = 0.0f;

    const int base_a = (n * 9) * HW + y * WW + x0;

    #pragma unroll
    for (int i = 0; i < 9; i++) {
        const int dy = (i < 3) ? 1 : ((i < 6) ? 0 : -1);
        const int m3 = i - (i / 3) * 3;
        const int dx = (m3 == 0) ? 1 : ((m3 == 1) ? 0 : -1);

        const int yb  = y - dy;
        const bool yok = ((unsigned)yb < (unsigned)HH);

        float a1[PPT], a2[PPT];
        ld8(a1, f01f + base_a + i * HW);
        ld8(a2, f12f + base_a + i * HW);

        const int bbase = (n * 9 + (8 - i)) * HW + (yok ? yb : 0) * WW;

        float w1[PPT], w2[PPT];
        if (yok) { ld8(w1, f10b + bbase + x0); ld8(w2, f21b + bbase + x0); }
        else {
            #pragma unroll
            for (int j = 0; j < PPT; j++) { w1[j] = 0.0f; w2[j] = 0.0f; }
        }

        float b1[PPT], b2[PPT];
        if (dx == 0) {
            #pragma unroll
            for (int j = 0; j < PPT; j++) { b1[j] = w1[j]; b2[j] = w2[j]; }
        } else if (dx == 1) {
            // need cols x0-1 .. x0+6
            float s1 = 0.f, s2 = 0.f;
            if (yok && x0 > 0) { s1 = f10b[bbase + x0 - 1]; s2 = f21b[bbase + x0 - 1]; }
            b1[0] = s1; b2[0] = s2;
            #pragma unroll
            for (int j = 1; j < PPT; j++) { b1[j] = w1[j-1]; b2[j] = w2[j-1]; }
        } else { // dx == -1: need cols x0+1 .. x0+8
            float s1 = 0.f, s2 = 0.f;
            if (yok && x0 + PPT < WW) { s1 = f10b[bbase + x0 + PPT]; s2 = f21b[bbase + x0 + PPT]; }
            #pragma unroll
            for (int j = 0; j < PPT - 1; j++) { b1[j] = w1[j+1]; b2[j] = w2[j+1]; }
            b1[PPT-1] = s1; b2[PPT-1] = s2;
        }

        #pragma unroll
        for (int j = 0; j < PPT; j++) {
            const int xb = x0 + j - dx;
            const bool ok = yok && ((unsigned)xb < (unsigned)WW);
            if (ok) {
                const float d1 = clipf(a1[j]) - clipf(b1[j]);
                const float d2 = clipf(a2[j]) - clipf(b2[j]);
                csum[j] += d1 * d1 + d2 * d2;
            }
        }
    }

    #pragma unroll
    for (int j = 0; j < PPT; j++)
        acc += mm[j] * csum[j] * (1.0f / 9.0f);

    // ---- block reduction ----
    #pragma unroll
    for (int off = 16; off > 0; off >>= 1)
        acc += __shfl_down_sync(0xFFFFFFFFu, acc, off);

    __shared__ float warp_sums[8];
    __shared__ bool  is_last;
    const int lane = threadIdx.x & 31;
    const int wid  = threadIdx.x >> 5;
    if (lane == 0) warp_sums[wid] = acc;
    __syncthreads();

    if (wid == 0) {
        float v = (lane < 8) ? warp_sums[lane] : 0.0f;
        #pragma unroll
        for (int off = 4; off > 0; off >>= 1)
            v += __shfl_down_sync(0xFFFFFFFFu, v, off);
        if (lane == 0) {
            atomicAdd(&g_acc, (double)v);
            __threadfence();
            const unsigned int ticket = atomicAdd(&g_ticket, 1u);
            is_last = (ticket == (unsigned int)(NBLOCKS - 1));
        }
    }
    __syncthreads();

    // Last block: publish result, reset state for next graph replay.
    if (is_last && threadIdx.x == 0) {
        __threadfence();
        out[0] = (float)g_acc;
        g_acc = 0.0;
        g_ticket = 0u;
    }
}

extern "C" void kernel_launch(void* const* d_in, const int* in_sizes, int n_in,
                              void* d_out, int out_size) {
    const float* roi  = (const float*)d_in[0];
    // d_in[1] boundary_mask: unused by reference
    const float* hm0  = (const float*)d_in[2];
    const float* hm1  = (const float*)d_in[3];
    const float* hm2  = (const float*)d_in[4];
    const float* r1pf = (const float*)d_in[5];
    const float* r1pb = (const float*)d_in[6];
    const float* r1nf = (const float*)d_in[7];
    const float* r1nb = (const float*)d_in[8];
    const float* r0f  = (const float*)d_in[9];
    const float* r0b  = (const float*)d_in[10];
    const float* r2f  = (const float*)d_in[11];
    const float* r2b  = (const float*)d_in[12];
    const float* f01f = (const float*)d_in[13];
    const float* f10b = (const float*)d_in[14];
    const float* f12f = (const float*)d_in[15];
    const float* f21b = (const float*)d_in[16];

    flow_loss_kernel<<<NBLOCKS, 256>>>(
        roi, hm0, hm1, hm2,
        r1pf, r1pb, r1nf, r1nb,
        r0f, r0b, r2f, r2b,
        f01f, f10b, f12f, f21b,
        (float*)d_out);
}